// round 9
// baseline (speedup 1.0000x reference)
#include <cuda_runtime.h>

#define P_DIM    128
#define NUK      8
#define NBLK     600                  // 8 u_k + 592 worker blocks (4/SM + 8 overhang, as R2)
#define NCHUNK   1184                 // fixed row chunks (determinism unit)
#define GRPSZ    74
#define NGRP     16                   // 1184 / 74
#define NTH      256
#define FIN_TARGET (NGRP + NUK)       // 24

// Scratch (no device allocation allowed)
__device__ float g_pmu[NCHUNK * P_DIM];   // per-CHUNK column sums of mu_N (fixed mapping)
__device__ float g_ps [NCHUNK * 8];       // per-CHUNK {pH,nH,pHc,nHc,pS,nS,pSc,nSc}
__device__ float g_y  [NGRP * P_DIM];     // per-group y_g = W1 @ m_g
__device__ float g_s2 [NGRP * 8];         // per-group scalar sums
__device__ float g_u  [NUK * P_DIM];      // u_k = W_even @ relu(+/- W_odd)
__device__ int   g_tick;                  // work-stealing ticket
__device__ int   g_cnt_grp[NGRP];
__device__ int   g_cnt_fin;
__device__ int   g_cnt_exit;              // last-exiting block resets everything

// warp-per-row matvec: 8 warps x 16 rows = 128 outputs; v4 = shared vector (32 float4)
__device__ __forceinline__ void matvec128(const float* __restrict__ W,
                                          const float4* __restrict__ v4,
                                          float* __restrict__ dst,
                                          int wrp, int lane)
{
    float4 v = v4[lane];
#pragma unroll
    for (int t = 0; t < 16; t += 2) {
        const int j0 = wrp * 16 + t;
        float4 w0 = reinterpret_cast<const float4*>(W + (size_t)j0       * P_DIM)[lane];
        float4 w1 = reinterpret_cast<const float4*>(W + (size_t)(j0 + 1) * P_DIM)[lane];
        float a0 = w0.x * v.x + w0.y * v.y + w0.z * v.z + w0.w * v.w;
        float a1 = w1.x * v.x + w1.y * v.y + w1.z * v.z + w1.w * v.w;
#pragma unroll
        for (int o = 16; o; o >>= 1) {
            a0 += __shfl_xor_sync(0xffffffffu, a0, o);
            a1 += __shfl_xor_sync(0xffffffffu, a1, o);
        }
        if (lane == 0) { dst[j0] = a0; dst[j0 + 1] = a1; }
    }
}

// final combiner: identical math to R2
__device__ __forceinline__ void final_combine(
    const float* __restrict__ xi, const float* __restrict__ W10,
    float* __restrict__ out, float* scal, int tid)
{
    if (tid < 8) {
        float t = 0.f;
#pragma unroll
        for (int g = 0; g < NGRP; g++) t += g_s2[g * 8 + tid];
        scal[tid] = t;   // [pH,nH,pHc,nHc,pS,nS,pSc,nSc]
    }
    __syncthreads();
    if (tid < P_DIM) {
        float t = 0.f;
#pragma unroll
        for (int g = 0; g < NGRP; g++) t += g_y[g * P_DIM + tid];
#pragma unroll
        for (int k = 0; k < NUK; k++) t += scal[k] * g_u[k * P_DIM + tid];
        t += W10[tid * 3 + 0] * xi[0]
           + W10[tid * 3 + 1] * xi[1]
           + W10[tid * 3 + 2] * xi[2];
        out[tid] = fmaxf(t, 0.f);
    }
}

__global__ __launch_bounds__(NTH) void k_fused(
    const float* __restrict__ xi,  const float* __restrict__ mu,
    const float* __restrict__ h,   const float* __restrict__ hc,
    const float* __restrict__ s,   const float* __restrict__ sc,
    const float* __restrict__ W1,  const float* __restrict__ W2,
    const float* __restrict__ W3,  const float* __restrict__ W4,
    const float* __restrict__ W5,  const float* __restrict__ W6,
    const float* __restrict__ W7,  const float* __restrict__ W8,
    const float* __restrict__ W9,  const float* __restrict__ W10,
    float* __restrict__ out, int N)
{
    __shared__ __align__(16) float sh[8 * P_DIM];
    __shared__ __align__(16) float vec[P_DIM];
    __shared__ float sw[8][8];
    __shared__ float scal[8];
    __shared__ int   s_flag;
    __shared__ int   s_chunk;

    const int tid  = threadIdx.x;
    const int lane = tid & 31;
    const int wrp  = tid >> 5;        // 0..7
    const int bid  = blockIdx.x;

    // ---------------- u_k precompute (blocks 0..7), then they join stealing ----------------
    if (bid < NUK) {
        const int  k   = bid;
        const int  p   = k >> 1;
        const bool neg = k & 1;
        const float* Wo = (p == 0) ? W3 : (p == 1) ? W5 : (p == 2) ? W7 : W9;
        const float* We = (p == 0) ? W2 : (p == 1) ? W4 : (p == 2) ? W6 : W8;
        if (tid < P_DIM) {
            float w = Wo[tid];
            vec[tid] = neg ? fminf(w, 0.f) : fmaxf(w, 0.f);
        }
        __syncthreads();
        matvec128(We, (const float4*)vec, &g_u[k * P_DIM], wrp, lane);

        __threadfence();
        __syncthreads();
        if (tid == 0) s_flag = (atomicAdd(&g_cnt_fin, 1) == FIN_TARGET - 1);
        __syncthreads();
        if (s_flag) { final_combine(xi, W10, out, scal, tid); }   // defensive; won't fire here
    }

    const int per = (N + NCHUNK - 1) / NCHUNK;   // 169
    const float4* mu4 = reinterpret_cast<const float4*>(mu);  // row stride = 32 float4

    // ---------------- work-stealing chunk loop ----------------
    for (;;) {
        __syncthreads();                              // smem / s_chunk reuse guard
        if (tid == 0) s_chunk = atomicAdd(&g_tick, 1);
        __syncthreads();
        const int c = s_chunk;
        if (c >= NCHUNK) break;

        const int r0 = c * per;
        const int r1 = min(r0 + per, N);

        // ---- stream (R2-proven loop) over chunk rows ----
        float a0 = 0.f, a1 = 0.f, a2 = 0.f, a3 = 0.f;
        int r = r0 + wrp;
        for (; r + 24 < r1; r += 32) {
            float4 v0 = mu4[(size_t)(r     ) * 32 + lane];
            float4 v1 = mu4[(size_t)(r +  8) * 32 + lane];
            float4 v2 = mu4[(size_t)(r + 16) * 32 + lane];
            float4 v3 = mu4[(size_t)(r + 24) * 32 + lane];
            a0 += v0.x + v1.x + v2.x + v3.x;
            a1 += v0.y + v1.y + v2.y + v3.y;
            a2 += v0.z + v1.z + v2.z + v3.z;
            a3 += v0.w + v1.w + v2.w + v3.w;
        }
        for (; r < r1; r += 8) {
            float4 v = mu4[(size_t)r * 32 + lane];
            a0 += v.x; a1 += v.y; a2 += v.z; a3 += v.w;
        }
        sh[wrp * P_DIM + lane * 4 + 0] = a0;
        sh[wrp * P_DIM + lane * 4 + 1] = a1;
        sh[wrp * P_DIM + lane * 4 + 2] = a2;
        sh[wrp * P_DIM + lane * 4 + 3] = a3;

        // ---- scalar pos/neg sums over chunk rows ----
        float ph = 0.f, nh = 0.f, phc = 0.f, nhc = 0.f;
        float ps = 0.f, ns = 0.f, psc = 0.f, nsc = 0.f;
        for (int i = r0 + tid; i < r1; i += NTH) {
            float v;
            v = h[i];  if (v > 0.f) ph  += v; else nh  += v;
            v = hc[i]; if (v > 0.f) phc += v; else nhc += v;
            v = s[i];  if (v > 0.f) ps  += v; else ns  += v;
            v = sc[i]; if (v > 0.f) psc += v; else nsc += v;
        }
#pragma unroll
        for (int o = 16; o; o >>= 1) {
            ph  += __shfl_xor_sync(0xffffffffu, ph,  o);
            nh  += __shfl_xor_sync(0xffffffffu, nh,  o);
            phc += __shfl_xor_sync(0xffffffffu, phc, o);
            nhc += __shfl_xor_sync(0xffffffffu, nhc, o);
            ps  += __shfl_xor_sync(0xffffffffu, ps,  o);
            ns  += __shfl_xor_sync(0xffffffffu, ns,  o);
            psc += __shfl_xor_sync(0xffffffffu, psc, o);
            nsc += __shfl_xor_sync(0xffffffffu, nsc, o);
        }
        if (lane == 0) {
            sw[wrp][0] = ph;  sw[wrp][1] = nh;
            sw[wrp][2] = phc; sw[wrp][3] = nhc;
            sw[wrp][4] = ps;  sw[wrp][5] = ns;
            sw[wrp][6] = psc; sw[wrp][7] = nsc;
        }
        __syncthreads();

        if (tid < P_DIM) {
            float t = 0.f;
#pragma unroll
            for (int i = 0; i < 8; i++) t += sh[i * P_DIM + tid];
            g_pmu[(size_t)c * P_DIM + tid] = t;
        }
        if (tid < 8) {
            float t = 0.f;
#pragma unroll
            for (int i = 0; i < 8; i++) t += sw[i][tid];
            g_ps[c * 8 + tid] = t;
        }

        // ---- group completion gate ----
        __threadfence();
        __syncthreads();
        const int grp = c / GRPSZ;
        if (tid == 0) s_flag = (atomicAdd(&g_cnt_grp[grp], 1) == GRPSZ - 1);
        __syncthreads();

        if (s_flag) {
            // ---- group leader: reduce 74 chunk-partials, y_g = W1 @ m_g ----
            const int base = grp * GRPSZ;
            if (tid < P_DIM) {
                float t = 0.f;
#pragma unroll 8
                for (int i = 0; i < GRPSZ; i++) t += g_pmu[(size_t)(base + i) * P_DIM + tid];
                vec[tid] = t;
            }
            if (tid < 8) {
                float t = 0.f;
#pragma unroll 8
                for (int i = 0; i < GRPSZ; i++) t += g_ps[(base + i) * 8 + tid];
                g_s2[grp * 8 + tid] = t;
            }
            __syncthreads();
            matvec128(W1, (const float4*)vec, &g_y[grp * P_DIM], wrp, lane);

            // ---- fin gate ----
            __threadfence();
            __syncthreads();
            if (tid == 0) s_flag = (atomicAdd(&g_cnt_fin, 1) == FIN_TARGET - 1);
            __syncthreads();
            if (s_flag) { final_combine(xi, W10, out, scal, tid); }
        }
    }

    // ---------------- last block OUT resets all control state ----------------
    __syncthreads();
    if (tid == 0) {
        __threadfence();
        if (atomicAdd(&g_cnt_exit, 1) == NBLK - 1) {
            g_tick = 0;
#pragma unroll
            for (int g = 0; g < NGRP; g++) g_cnt_grp[g] = 0;
            g_cnt_fin  = 0;
            g_cnt_exit = 0;
        }
    }
}

extern "C" void kernel_launch(void* const* d_in, const int* in_sizes, int n_in,
                              void* d_out, int out_size)
{
    const float* xi  = (const float*)d_in[0];
    const float* muN = (const float*)d_in[1];
    const float* h   = (const float*)d_in[2];
    const float* hc  = (const float*)d_in[3];
    const float* s   = (const float*)d_in[4];
    const float* sc  = (const float*)d_in[5];
    const float* W1  = (const float*)d_in[6];
    const float* W2  = (const float*)d_in[7];
    const float* W3  = (const float*)d_in[8];
    const float* W4  = (const float*)d_in[9];
    const float* W5  = (const float*)d_in[10];
    const float* W6  = (const float*)d_in[11];
    const float* W7  = (const float*)d_in[12];
    const float* W8  = (const float*)d_in[13];
    const float* W9  = (const float*)d_in[14];
    const float* W10 = (const float*)d_in[15];
    float* out = (float*)d_out;

    const int N = in_sizes[2];

    k_fused<<<NBLK, NTH>>>(xi, muN, h, hc, s, sc,
                           W1, W2, W3, W4, W5, W6, W7, W8, W9, W10,
                           out, N);
}

// round 10
// speedup vs baseline: 1.7134x; 1.7134x over previous
#include <cuda_runtime.h>

#define P_DIM    128
#define NUK      8                    // 8 weight-only u_k vectors
#define NSTREAM  592                  // stream blocks (4/SM wave + 8 overhang)
#define GRPSZ    37
#define NGRP     16                   // 592 / 37
#define NBLK     (NUK + NSTREAM)      // 600
#define NTH      256
#define FIN_TARGET (NGRP + NUK)       // 24 contributions to the final stage
#define NLATE    8                    // last 8 stream blocks start late (overhang)
#define DISC     40                   // row discount for late blocks (~2.3us)

// Scratch (no device allocation allowed)
__device__ float g_pmu[NSTREAM * P_DIM];   // per-stream-block column sums of mu_N
__device__ float g_ps [NSTREAM * 8];       // per-stream-block {pH,nH,pHc,nHc,pS,nS,pSc,nSc}
__device__ float g_y  [NGRP * P_DIM];      // per-group y_g = W1 @ m_g
__device__ float g_s2 [NGRP * 8];          // per-group scalar sums
__device__ float g_u  [NUK * P_DIM];       // u_k = W_even @ relu(+/- W_odd)
__device__ int   g_cnt_grp[NGRP];          // zero-initialized; reset by final block
__device__ int   g_cnt_fin;

// warp-per-row matvec: 8 warps x 16 rows = 128 outputs; v4 = shared vector (32 float4)
__device__ __forceinline__ void matvec128(const float* __restrict__ W,
                                          const float4* __restrict__ v4,
                                          float* __restrict__ dst,
                                          int wrp, int lane)
{
    float4 v = v4[lane];
#pragma unroll
    for (int t = 0; t < 16; t += 2) {
        const int j0 = wrp * 16 + t;
        float4 w0 = reinterpret_cast<const float4*>(W + (size_t)j0       * P_DIM)[lane];
        float4 w1 = reinterpret_cast<const float4*>(W + (size_t)(j0 + 1) * P_DIM)[lane];
        float a0 = w0.x * v.x + w0.y * v.y + w0.z * v.z + w0.w * v.w;
        float a1 = w1.x * v.x + w1.y * v.y + w1.z * v.z + w1.w * v.w;
#pragma unroll
        for (int o = 16; o; o >>= 1) {
            a0 += __shfl_xor_sync(0xffffffffu, a0, o);
            a1 += __shfl_xor_sync(0xffffffffu, a1, o);
        }
        if (lane == 0) { dst[j0] = a0; dst[j0 + 1] = a1; }
    }
}

__global__ __launch_bounds__(NTH) void k_fused(
    const float* __restrict__ xi,  const float* __restrict__ mu,
    const float* __restrict__ h,   const float* __restrict__ hc,
    const float* __restrict__ s,   const float* __restrict__ sc,
    const float* __restrict__ W1,  const float* __restrict__ W2,
    const float* __restrict__ W3,  const float* __restrict__ W4,
    const float* __restrict__ W5,  const float* __restrict__ W6,
    const float* __restrict__ W7,  const float* __restrict__ W8,
    const float* __restrict__ W9,  const float* __restrict__ W10,
    float* __restrict__ out, int N)
{
    __shared__ __align__(16) float sh[8 * P_DIM];   // streaming warp partials
    __shared__ __align__(16) float vec[P_DIM];      // matvec input vector
    __shared__ float sw[8][8];
    __shared__ float scal[8];
    __shared__ int   s_flag;

    const int tid  = threadIdx.x;
    const int lane = tid & 31;
    const int wrp  = tid >> 5;        // 0..7
    const int bid  = blockIdx.x;

    bool do_fin = false;

    if (bid < NUK) {
        // ---------------- u_k blocks: weight-only precompute ----------------
        const int  k   = bid;
        const int  p   = k >> 1;
        const bool neg = k & 1;
        const float* Wo = (p == 0) ? W3 : (p == 1) ? W5 : (p == 2) ? W7 : W9;
        const float* We = (p == 0) ? W2 : (p == 1) ? W4 : (p == 2) ? W6 : W8;
        if (tid < P_DIM) {
            float w = Wo[tid];
            vec[tid] = neg ? fminf(w, 0.f) : fmaxf(w, 0.f);
        }
        __syncthreads();
        matvec128(We, (const float4*)vec, &g_u[k * P_DIM], wrp, lane);
        do_fin = true;
    } else {
        // ---------------- streaming blocks ----------------
        const int sb  = bid - NUK;            // 0..591
        const int grp = sb / GRPSZ;
        // blocks sb >= 584 (grid IDs 592..599) start late -> DISC fewer rows
        const int nEarly = NSTREAM - NLATE;   // 584
        const int per    = (N + NLATE * DISC + NSTREAM - 1) / NSTREAM;  // early-block rows
        const int perL   = per - DISC;        // late-block rows
        const int r0 = (sb < nEarly) ? sb * per
                                     : nEarly * per + (sb - nEarly) * perL;
        const int r1 = min(r0 + ((sb < nEarly) ? per : perL), N);

        // mu_N column sums: thread owns cols [4*lane .. 4*lane+3], warp = 1 row/iter
        float a0 = 0.f, a1 = 0.f, a2 = 0.f, a3 = 0.f;
        const float4* mu4 = reinterpret_cast<const float4*>(mu);  // row stride = 32 float4
        int r = r0 + wrp;
        for (; r + 24 < r1; r += 32) {
            float4 v0 = mu4[(size_t)(r     ) * 32 + lane];
            float4 v1 = mu4[(size_t)(r +  8) * 32 + lane];
            float4 v2 = mu4[(size_t)(r + 16) * 32 + lane];
            float4 v3 = mu4[(size_t)(r + 24) * 32 + lane];
            a0 += v0.x + v1.x + v2.x + v3.x;
            a1 += v0.y + v1.y + v2.y + v3.y;
            a2 += v0.z + v1.z + v2.z + v3.z;
            a3 += v0.w + v1.w + v2.w + v3.w;
        }
        for (; r < r1; r += 8) {
            float4 v = mu4[(size_t)r * 32 + lane];
            a0 += v.x; a1 += v.y; a2 += v.z; a3 += v.w;
        }
        sh[wrp * P_DIM + lane * 4 + 0] = a0;
        sh[wrp * P_DIM + lane * 4 + 1] = a1;
        sh[wrp * P_DIM + lane * 4 + 2] = a2;
        sh[wrp * P_DIM + lane * 4 + 3] = a3;

        // scalar pos/neg sums of h, hc, s, sc
        float ph = 0.f, nh = 0.f, phc = 0.f, nhc = 0.f;
        float ps = 0.f, ns = 0.f, psc = 0.f, nsc = 0.f;
        for (int i = r0 + tid; i < r1; i += NTH) {
            float v;
            v = h[i];  if (v > 0.f) ph  += v; else nh  += v;
            v = hc[i]; if (v > 0.f) phc += v; else nhc += v;
            v = s[i];  if (v > 0.f) ps  += v; else ns  += v;
            v = sc[i]; if (v > 0.f) psc += v; else nsc += v;
        }
#pragma unroll
        for (int o = 16; o; o >>= 1) {
            ph  += __shfl_xor_sync(0xffffffffu, ph,  o);
            nh  += __shfl_xor_sync(0xffffffffu, nh,  o);
            phc += __shfl_xor_sync(0xffffffffu, phc, o);
            nhc += __shfl_xor_sync(0xffffffffu, nhc, o);
            ps  += __shfl_xor_sync(0xffffffffu, ps,  o);
            ns  += __shfl_xor_sync(0xffffffffu, ns,  o);
            psc += __shfl_xor_sync(0xffffffffu, psc, o);
            nsc += __shfl_xor_sync(0xffffffffu, nsc, o);
        }
        if (lane == 0) {
            sw[wrp][0] = ph;  sw[wrp][1] = nh;
            sw[wrp][2] = phc; sw[wrp][3] = nhc;
            sw[wrp][4] = ps;  sw[wrp][5] = ns;
            sw[wrp][6] = psc; sw[wrp][7] = nsc;
        }
        __syncthreads();

        if (tid < P_DIM) {
            float t = 0.f;
#pragma unroll
            for (int i = 0; i < 8; i++) t += sh[i * P_DIM + tid];
            g_pmu[sb * P_DIM + tid] = t;
        }
        if (tid < 8) {
            float t = 0.f;
#pragma unroll
            for (int i = 0; i < 8; i++) t += sw[i][tid];
            g_ps[sb * 8 + tid] = t;
        }

        // group completion check (threadfence-reduction pattern)
        __threadfence();
        __syncthreads();
        if (tid == 0) s_flag = (atomicAdd(&g_cnt_grp[grp], 1) == GRPSZ - 1);
        __syncthreads();

        if (s_flag) {
            // ---- group leader: reduce 37 partials, y_g = W1 @ m_g ----
            const int base = grp * GRPSZ;
            if (tid < P_DIM) {
                float t = 0.f;
#pragma unroll
                for (int i = 0; i < GRPSZ; i++) t += g_pmu[(base + i) * P_DIM + tid];
                vec[tid] = t;
            }
            if (tid < 8) {
                float t = 0.f;
#pragma unroll
                for (int i = 0; i < GRPSZ; i++) t += g_ps[(base + i) * 8 + tid];
                g_s2[grp * 8 + tid] = t;
            }
            __syncthreads();
            matvec128(W1, (const float4*)vec, &g_y[grp * P_DIM], wrp, lane);
            do_fin = true;
        }
    }

    if (do_fin) {
        __threadfence();
        __syncthreads();
        if (tid == 0) s_flag = (atomicAdd(&g_cnt_fin, 1) == FIN_TARGET - 1);
        __syncthreads();

        if (s_flag) {
            // ---------------- final combiner (tiny) ----------------
            if (tid < 8) {
                float t = 0.f;
#pragma unroll
                for (int g = 0; g < NGRP; g++) t += g_s2[g * 8 + tid];
                scal[tid] = t;   // [pH,nH,pHc,nHc,pS,nS,pSc,nSc]
            }
            __syncthreads();
            if (tid < P_DIM) {
                float t = 0.f;
#pragma unroll
                for (int g = 0; g < NGRP; g++) t += g_y[g * P_DIM + tid];
#pragma unroll
                for (int k = 0; k < NUK; k++) t += scal[k] * g_u[k * P_DIM + tid];
                t += W10[tid * 3 + 0] * xi[0]
                   + W10[tid * 3 + 1] * xi[1]
                   + W10[tid * 3 + 2] * xi[2];
                out[tid] = fmaxf(t, 0.f);
            }
            // reset counters for next graph replay (all work already consumed)
            if (tid < NGRP) g_cnt_grp[tid] = 0;
            if (tid == 0)   g_cnt_fin = 0;
        }
    }
}

extern "C" void kernel_launch(void* const* d_in, const int* in_sizes, int n_in,
                              void* d_out, int out_size)
{
    const float* xi  = (const float*)d_in[0];
    const float* muN = (const float*)d_in[1];
    const float* h   = (const float*)d_in[2];
    const float* hc  = (const float*)d_in[3];
    const float* s   = (const float*)d_in[4];
    const float* sc  = (const float*)d_in[5];
    const float* W1  = (const float*)d_in[6];
    const float* W2  = (const float*)d_in[7];
    const float* W3  = (const float*)d_in[8];
    const float* W4  = (const float*)d_in[9];
    const float* W5  = (const float*)d_in[10];
    const float* W6  = (const float*)d_in[11];
    const float* W7  = (const float*)d_in[12];
    const float* W8  = (const float*)d_in[13];
    const float* W9  = (const float*)d_in[14];
    const float* W10 = (const float*)d_in[15];
    float* out = (float*)d_out;

    const int N = in_sizes[2];

    k_fused<<<NBLK, NTH>>>(xi, muN, h, hc, s, sc,
                           W1, W2, W3, W4, W5, W6, W7, W8, W9, W10,
                           out, N);
}